// round 1
// baseline (speedup 1.0000x reference)
#include <cuda_runtime.h>

#define NN 10000
#define EE 160000
#define TE (EE + NN)
#define DIN 768
#define DH 128
#define HEADS 4

// ---------------- scratch (static device globals; no allocation) ----------------
__device__ float d_xp[NN * DH];
__device__ float d_gp[NN * DH];
__device__ float d_h1[NN * HEADS * DH];
__device__ float d_out1[NN * HEADS * DH];
__device__ float d_h2[NN * DH];
__device__ float d_hin[NN * DH];
__device__ float d_as1[NN * HEADS];
__device__ float d_ad1[NN * HEADS];
__device__ float d_as2[NN];
__device__ float d_ad2[NN];
__device__ int d_deg[NN];
__device__ int d_offs[NN + 1];
__device__ int d_fill[NN];
__device__ int d_csr[TE];

// ---------------- graph build ----------------
__global__ void zero_kernel() {
    int i = blockIdx.x * blockDim.x + threadIdx.x;
    if (i < NN) { d_deg[i] = 0; d_fill[i] = 0; }
}

__global__ void hist_kernel(const int* __restrict__ ei) {
    int e = blockIdx.x * blockDim.x + threadIdx.x;
    if (e >= TE) return;
    int dst = (e < EE) ? ei[EE + e] : (e - EE);
    atomicAdd(&d_deg[dst], 1);
}

__global__ void scan_kernel() {
    __shared__ int part[1024];
    int tid = threadIdx.x;
    const int CH = 10;  // 1024*10 >= 10000
    int base = tid * CH;
    int loc[CH];
    int s = 0;
#pragma unroll
    for (int i = 0; i < CH; i++) {
        int v = (base + i < NN) ? d_deg[base + i] : 0;
        loc[i] = s;
        s += v;
    }
    part[tid] = s;
    __syncthreads();
    for (int off = 1; off < 1024; off <<= 1) {
        int v = (tid >= off) ? part[tid - off] : 0;
        __syncthreads();
        part[tid] += v;
        __syncthreads();
    }
    int pre = (tid > 0) ? part[tid - 1] : 0;
#pragma unroll
    for (int i = 0; i < CH; i++)
        if (base + i < NN) d_offs[base + i] = pre + loc[i];
    if (tid == 1023) d_offs[NN] = part[1023];
}

__global__ void scatter_kernel(const int* __restrict__ ei) {
    int e = blockIdx.x * blockDim.x + threadIdx.x;
    if (e >= TE) return;
    int src, dst;
    if (e < EE) { src = ei[e]; dst = ei[EE + e]; }
    else        { src = dst = e - EE; }
    int pos = d_offs[dst] + atomicAdd(&d_fill[dst], 1);
    d_csr[pos] = src;
}

// ---------------- GEMM: C[M,N] = A[M,K] @ B[K,N] (+bias) ----------------
// BM=128, BN=64, BK=16, 256 threads, 8x4 per-thread tile.
#define BM 128
#define BN 64
#define BK 16

__global__ __launch_bounds__(256) void gemm_kernel(
    const float* __restrict__ A, const float* __restrict__ B,
    const float* __restrict__ bias, float* __restrict__ C,
    int M, int N, int K)
{
    __shared__ float As[BK][BM + 4];
    __shared__ float Bs[BK][BN];
    int tid = threadIdx.x;
    int m0 = blockIdx.x * BM;
    int n0 = blockIdx.y * BN;
    int tx = tid & 15;   // col group 0..15
    int ty = tid >> 4;   // row group 0..15
    int ar = tid >> 2;          // 0..63
    int ac = (tid & 3) * 4;     // 0,4,8,12
    int br = tid >> 4;          // 0..15
    int bc = (tid & 15) * 4;    // 0..60

    float acc[8][4] = {};

    for (int k0 = 0; k0 < K; k0 += BK) {
#pragma unroll
        for (int h = 0; h < 2; h++) {
            int r = ar + h * 64;
            float4 v = make_float4(0.f, 0.f, 0.f, 0.f);
            if (m0 + r < M)
                v = *(const float4*)&A[(size_t)(m0 + r) * K + k0 + ac];
            As[ac + 0][r] = v.x;
            As[ac + 1][r] = v.y;
            As[ac + 2][r] = v.z;
            As[ac + 3][r] = v.w;
        }
        float4 bv = *(const float4*)&B[(size_t)(k0 + br) * N + n0 + bc];
        *(float4*)&Bs[br][bc] = bv;
        __syncthreads();
#pragma unroll
        for (int k = 0; k < BK; k++) {
            float a[8], b[4];
            *(float4*)&a[0] = *(float4*)&As[k][ty * 8];
            *(float4*)&a[4] = *(float4*)&As[k][ty * 8 + 4];
            *(float4*)&b[0] = *(float4*)&Bs[k][tx * 4];
#pragma unroll
            for (int i = 0; i < 8; i++)
#pragma unroll
                for (int j = 0; j < 4; j++)
                    acc[i][j] += a[i] * b[j];
        }
        __syncthreads();
    }

#pragma unroll
    for (int i = 0; i < 8; i++) {
        int m = m0 + ty * 8 + i;
        if (m >= M) continue;
#pragma unroll
        for (int j = 0; j < 4; j++) {
            int n = n0 + tx * 4 + j;
            float v = acc[i][j];
            if (bias) v += bias[n];
            C[(size_t)m * N + n] = v;
        }
    }
}

// ---------------- attention logits: a_src/a_dst = <h[n,h,:], att> ----------------
template <int H>
__global__ void attdot_kernel(const float* __restrict__ h,
                              const float* __restrict__ att_src,
                              const float* __restrict__ att_dst,
                              float* __restrict__ a_src,
                              float* __restrict__ a_dst)
{
    int gw = (blockIdx.x * blockDim.x + threadIdx.x) >> 5;
    if (gw >= NN * H) return;
    int lane = threadIdx.x & 31;
    int node = gw / H, hh = gw % H;
    const float* row = h + (size_t)node * (H * DH) + hh * DH;
    float s1 = 0.f, s2 = 0.f;
#pragma unroll
    for (int c = lane; c < DH; c += 32) {
        float v = row[c];
        s1 += v * att_src[hh * DH + c];
        s2 += v * att_dst[hh * DH + c];
    }
#pragma unroll
    for (int o = 16; o > 0; o >>= 1) {
        s1 += __shfl_xor_sync(0xffffffffu, s1, o);
        s2 += __shfl_xor_sync(0xffffffffu, s2, o);
    }
    if (lane == 0) { a_src[gw] = s1; a_dst[gw] = s2; }
}

// ---------------- GAT aggregation: warp per dst node ----------------
// ACT==1: out = elu(agg + bias)     (gat1)
// ACT==2: out = agg + bias + beta*gp (gat2 -> hin)
template <int H, int ACT>
__global__ void gat_agg_kernel(const float* __restrict__ hfeat,
                               const float* __restrict__ a_src,
                               const float* __restrict__ a_dst,
                               const float* __restrict__ bias,
                               const float* __restrict__ gp,
                               const float* __restrict__ beta,
                               float* __restrict__ out)
{
    constexpr int F = H * DH;
    constexpr int R = F / 32;
    int warp = (blockIdx.x * blockDim.x + threadIdx.x) >> 5;
    if (warp >= NN) return;
    int lane = threadIdx.x & 31;
    int n = warp;
    int start = d_offs[n], end = d_offs[n + 1];

    float adst[H];
#pragma unroll
    for (int hh = 0; hh < H; hh++) adst[hh] = a_dst[n * H + hh];

    // pass 1a: segment max of leaky(a_src + a_dst)
    float m[H];
#pragma unroll
    for (int hh = 0; hh < H; hh++) m[hh] = -1e30f;
    for (int j = start + lane; j < end; j += 32) {
        int s = d_csr[j];
#pragma unroll
        for (int hh = 0; hh < H; hh++) {
            float e = a_src[s * H + hh] + adst[hh];
            e = e > 0.f ? e : 0.2f * e;
            m[hh] = fmaxf(m[hh], e);
        }
    }
#pragma unroll
    for (int hh = 0; hh < H; hh++)
#pragma unroll
        for (int o = 16; o > 0; o >>= 1)
            m[hh] = fmaxf(m[hh], __shfl_xor_sync(0xffffffffu, m[hh], o));

    // pass 1b: segment sum of exp(e - m)
    float ssum[H] = {};
    for (int j = start + lane; j < end; j += 32) {
        int s = d_csr[j];
#pragma unroll
        for (int hh = 0; hh < H; hh++) {
            float e = a_src[s * H + hh] + adst[hh];
            e = e > 0.f ? e : 0.2f * e;
            ssum[hh] += __expf(e - m[hh]);
        }
    }
    float rinv[H];
#pragma unroll
    for (int hh = 0; hh < H; hh++) {
#pragma unroll
        for (int o = 16; o > 0; o >>= 1)
            ssum[hh] += __shfl_xor_sync(0xffffffffu, ssum[hh], o);
        rinv[hh] = 1.f / (ssum[hh] + 1e-16f);
    }

    // pass 2: weighted feature gather; alpha computed lane-parallel, shfl-broadcast
    float acc[R] = {};
    for (int jb = start; jb < end; jb += 32) {
        int j = jb + lane;
        int mys = 0;
        float myal[H];
#pragma unroll
        for (int hh = 0; hh < H; hh++) myal[hh] = 0.f;
        if (j < end) {
            mys = d_csr[j];
#pragma unroll
            for (int hh = 0; hh < H; hh++) {
                float e = a_src[mys * H + hh] + adst[hh];
                e = e > 0.f ? e : 0.2f * e;
                myal[hh] = __expf(e - m[hh]) * rinv[hh];
            }
        }
        int cnt = min(32, end - jb);
        for (int t = 0; t < cnt; t++) {
            int s = __shfl_sync(0xffffffffu, mys, t);
            float al[H];
#pragma unroll
            for (int hh = 0; hh < H; hh++)
                al[hh] = __shfl_sync(0xffffffffu, myal[hh], t);
            const float* hr = hfeat + (size_t)s * F;
#pragma unroll
            for (int r = 0; r < R; r++) {
                int f = r * 32 + lane;
                acc[r] += al[f / DH] * __ldg(&hr[f]);
            }
        }
    }

    // epilogue
#pragma unroll
    for (int r = 0; r < R; r++) {
        int f = r * 32 + lane;
        float v = acc[r] + bias[f];
        if (ACT == 1) {
            v = v > 0.f ? v : (__expf(v) - 1.f);  // ELU
        } else {
            v = v + beta[0] * gp[(size_t)n * F + f];
        }
        out[(size_t)n * F + f] = v;
    }
}

// ---------------- launch ----------------
extern "C" void kernel_launch(void* const* d_in, const int* in_sizes, int n_in,
                              void* d_out, int out_size)
{
    const float* x       = (const float*)d_in[0];
    const int*   ei      = (const int*)d_in[1];
    const float* g       = (const float*)d_in[2];
    const float* proj_W  = (const float*)d_in[3];
    const float* proj_b  = (const float*)d_in[4];
    const float* gat1_W  = (const float*)d_in[5];
    const float* gat1_as = (const float*)d_in[6];
    const float* gat1_ad = (const float*)d_in[7];
    const float* gat1_b  = (const float*)d_in[8];
    const float* gat2_W  = (const float*)d_in[9];
    const float* gat2_as = (const float*)d_in[10];
    const float* gat2_ad = (const float*)d_in[11];
    const float* gat2_b  = (const float*)d_in[12];
    const float* dec_W   = (const float*)d_in[13];
    const float* dec_b   = (const float*)d_in[14];
    const float* beta    = (const float*)d_in[15];
    float* out = (float*)d_out;

    float *xp, *gp, *h1, *out1, *h2, *hin, *as1, *ad1, *as2, *ad2;
    cudaGetSymbolAddress((void**)&xp,   d_xp);
    cudaGetSymbolAddress((void**)&gp,   d_gp);
    cudaGetSymbolAddress((void**)&h1,   d_h1);
    cudaGetSymbolAddress((void**)&out1, d_out1);
    cudaGetSymbolAddress((void**)&h2,   d_h2);
    cudaGetSymbolAddress((void**)&hin,  d_hin);
    cudaGetSymbolAddress((void**)&as1,  d_as1);
    cudaGetSymbolAddress((void**)&ad1,  d_ad1);
    cudaGetSymbolAddress((void**)&as2,  d_as2);
    cudaGetSymbolAddress((void**)&ad2,  d_ad2);

    // graph build (CSR by dst, with self loops)
    zero_kernel<<<(NN + 255) / 256, 256>>>();
    hist_kernel<<<(TE + 255) / 256, 256>>>(ei);
    scan_kernel<<<1, 1024>>>();
    scatter_kernel<<<(TE + 255) / 256, 256>>>(ei);

    dim3 blk(256);
    // xp = x @ proj_W + proj_b ; gp = g @ proj_W + proj_b
    gemm_kernel<<<dim3((NN + BM - 1) / BM, DH / BN), blk>>>(x, proj_W, proj_b, xp, NN, DH, DIN);
    gemm_kernel<<<dim3((NN + BM - 1) / BM, DH / BN), blk>>>(g, proj_W, proj_b, gp, NN, DH, DIN);

    // gat1: h1 = xp @ gat1_W  [10000, 512]
    gemm_kernel<<<dim3((NN + BM - 1) / BM, (HEADS * DH) / BN), blk>>>(xp, gat1_W, nullptr, h1, NN, HEADS * DH, DH);
    attdot_kernel<HEADS><<<(NN * HEADS * 32 + 255) / 256, 256>>>(h1, gat1_as, gat1_ad, as1, ad1);
    gat_agg_kernel<HEADS, 1><<<(NN * 32 + 255) / 256, 256>>>(h1, as1, ad1, gat1_b, nullptr, nullptr, out1);

    // gat2: h2 = out1 @ gat2_W  [10000, 128]
    gemm_kernel<<<dim3((NN + BM - 1) / BM, DH / BN), blk>>>(out1, gat2_W, nullptr, h2, NN, DH, HEADS * DH);
    attdot_kernel<1><<<(NN * 32 + 255) / 256, 256>>>(h2, gat2_as, gat2_ad, as2, ad2);
    gat_agg_kernel<1, 2><<<(NN * 32 + 255) / 256, 256>>>(h2, as2, ad2, gat2_b, gp, beta, hin);

    // decoder: out = hin @ dec_W + dec_b  [10000, 768]
    gemm_kernel<<<dim3((NN + BM - 1) / BM, DIN / BN), blk>>>(hin, dec_W, dec_b, out, NN, DIN, DH);
}

// round 3
// speedup vs baseline: 1.8950x; 1.8950x over previous
#include <cuda_runtime.h>

#define NN 10000
#define EE 160000
#define TE (EE + NN)
#define DIN 768
#define DH 128
#define HEADS 4

// ---------------- scratch (static device globals; no allocation) ----------------
__device__ float d_xp[NN * DH];
__device__ float d_gp[NN * DH];
__device__ float d_h1[NN * HEADS * DH];
__device__ float d_out1[NN * HEADS * DH];
__device__ float d_h2[NN * DH];
__device__ float d_hin[NN * DH];
__device__ float d_as1[NN * HEADS];
__device__ float d_ad1[NN * HEADS];
__device__ float d_as2[NN];
__device__ float d_ad2[NN];
__device__ int d_deg[NN];
__device__ int d_offs[NN + 1];
__device__ int d_fill[NN];
__device__ int d_csr[TE];

// ---------------- graph build ----------------
__global__ void zero_kernel() {
    int i = blockIdx.x * blockDim.x + threadIdx.x;
    if (i < NN) { d_deg[i] = 0; d_fill[i] = 0; }
}

__global__ void hist_kernel(const int* __restrict__ ei) {
    int e = blockIdx.x * blockDim.x + threadIdx.x;
    if (e >= TE) return;
    int dst = (e < EE) ? ei[EE + e] : (e - EE);
    atomicAdd(&d_deg[dst], 1);
}

__global__ void scan_kernel() {
    __shared__ int part[1024];
    int tid = threadIdx.x;
    const int CH = 10;  // 1024*10 >= 10000
    int base = tid * CH;
    int loc[CH];
    int s = 0;
#pragma unroll
    for (int i = 0; i < CH; i++) {
        int v = (base + i < NN) ? d_deg[base + i] : 0;
        loc[i] = s;
        s += v;
    }
    part[tid] = s;
    __syncthreads();
    for (int off = 1; off < 1024; off <<= 1) {
        int v = (tid >= off) ? part[tid - off] : 0;
        __syncthreads();
        part[tid] += v;
        __syncthreads();
    }
    int pre = (tid > 0) ? part[tid - 1] : 0;
#pragma unroll
    for (int i = 0; i < CH; i++)
        if (base + i < NN) d_offs[base + i] = pre + loc[i];
    if (tid == 1023) d_offs[NN] = part[1023];
}

__global__ void scatter_kernel(const int* __restrict__ ei) {
    int e = blockIdx.x * blockDim.x + threadIdx.x;
    if (e >= TE) return;
    int src, dst;
    if (e < EE) { src = ei[e]; dst = ei[EE + e]; }
    else        { src = dst = e - EE; }
    int pos = d_offs[dst] + atomicAdd(&d_fill[dst], 1);
    d_csr[pos] = src;
}

// ---------------- TF32 tensor-core GEMM ----------------
// C[M,N] = A[M,K] @ B[K,N] (+bias). BM=128, BN=64, BK=16.
// 256 threads = 8 warps (4 along M x 2 along N), warp tile 32x32
// = 2x4 atoms of mma.sync.m16n8k8 tf32.
// Double-buffered smem, fp32->tf32 conversion at smem store time.
// If A2 != nullptr, blockIdx.z selects (A,C) vs (A2,C2) — shared weights.

#define BM 128
#define BN 64
#define BK 16
#define APAD 20   // As row stride (floats): 8 rows x stride 20 distinct mod 32
#define BPAD 72   // Bs row stride: tig*72 mod 32 = tig*8 -> conflict-free

__device__ __forceinline__ unsigned f2tf(float x) {
    unsigned r;
    asm("cvt.rna.tf32.f32 %0, %1;" : "=r"(r) : "f"(x));
    return r;
}

__device__ __forceinline__ void mma_tf32(float c[4], const unsigned a[4], const unsigned b[2]) {
    asm volatile(
        "mma.sync.aligned.m16n8k8.row.col.f32.tf32.tf32.f32 "
        "{%0,%1,%2,%3}, {%4,%5,%6,%7}, {%8,%9}, {%0,%1,%2,%3};\n"
        : "+f"(c[0]), "+f"(c[1]), "+f"(c[2]), "+f"(c[3])
        : "r"(a[0]), "r"(a[1]), "r"(a[2]), "r"(a[3]), "r"(b[0]), "r"(b[1]));
}

__global__ __launch_bounds__(256) void gemm_tf32(
    const float* __restrict__ A, const float* __restrict__ B,
    const float* __restrict__ bias, float* __restrict__ C,
    int M, int N, int K,
    const float* __restrict__ A2 = nullptr, float* __restrict__ C2 = nullptr)
{
    __shared__ unsigned As[2][BM][APAD];
    __shared__ unsigned Bs[2][BK][BPAD];

    const float* Ause = A;
    float* Cuse = C;
    if (A2 != nullptr && blockIdx.z == 1) { Ause = A2; Cuse = C2; }

    int tid = threadIdx.x;
    int lane = tid & 31;
    int warp = tid >> 5;
    int wm = warp & 3;       // 0..3 (M dir)
    int wn = warp >> 2;      // 0..1 (N dir)
    int group = lane >> 2;   // 0..7
    int tig = lane & 3;      // 0..3

    int m0 = blockIdx.x * BM;
    int n0 = blockIdx.y * BN;

    // global->reg staging indices
    int arow0 = tid >> 2;          // A: row = tid>>2 (+64 per iter)
    int acol = (tid & 3) * 4;
    int brow = tid >> 4;           // B: row 0..15
    int bcol = (tid & 15) * 4;

    float4 av[2], bv;

    auto fetch = [&](int k0) {
#pragma unroll
        for (int it = 0; it < 2; it++) {
            int r = arow0 + it * 64;
            av[it] = make_float4(0.f, 0.f, 0.f, 0.f);
            if (m0 + r < M)
                av[it] = *(const float4*)&Ause[(size_t)(m0 + r) * K + k0 + acol];
        }
        bv = *(const float4*)&B[(size_t)(k0 + brow) * N + n0 + bcol];
    };
    auto stage = [&](int buf) {
#pragma unroll
        for (int it = 0; it < 2; it++) {
            int r = arow0 + it * 64;
            unsigned* p = &As[buf][r][acol];
            p[0] = f2tf(av[it].x); p[1] = f2tf(av[it].y);
            p[2] = f2tf(av[it].z); p[3] = f2tf(av[it].w);
        }
        unsigned* q = &Bs[buf][brow][bcol];
        q[0] = f2tf(bv.x); q[1] = f2tf(bv.y); q[2] = f2tf(bv.z); q[3] = f2tf(bv.w);
    };

    float acc[2][4][4] = {};

    fetch(0);
    stage(0);
    __syncthreads();

    int nk = K / BK;
    for (int i = 0; i < nk; i++) {
        int cur = i & 1;
        if (i + 1 < nk) fetch((i + 1) * BK);

#pragma unroll
        for (int ks = 0; ks < BK; ks += 8) {
            unsigned afr[2][4], bfr[4][2];
#pragma unroll
            for (int ma = 0; ma < 2; ma++) {
                int rb = wm * 32 + ma * 16;
                afr[ma][0] = As[cur][rb + group][ks + tig];
                afr[ma][1] = As[cur][rb + group + 8][ks + tig];
                afr[ma][2] = As[cur][rb + group][ks + tig + 4];
                afr[ma][3] = As[cur][rb + group + 8][ks + tig + 4];
            }
#pragma unroll
            for (int na = 0; na < 4; na++) {
                int cb = wn * 32 + na * 8 + group;
                bfr[na][0] = Bs[cur][ks + tig][cb];
                bfr[na][1] = Bs[cur][ks + tig + 4][cb];
            }
#pragma unroll
            for (int ma = 0; ma < 2; ma++)
#pragma unroll
                for (int na = 0; na < 4; na++)
                    mma_tf32(acc[ma][na], afr[ma], bfr[na]);
        }

        if (i + 1 < nk) stage(cur ^ 1);
        __syncthreads();
    }

    // epilogue
#pragma unroll
    for (int ma = 0; ma < 2; ma++) {
        int r0 = m0 + wm * 32 + ma * 16 + group;
#pragma unroll
        for (int na = 0; na < 4; na++) {
            int col = n0 + wn * 32 + na * 8 + tig * 2;
            float b0 = bias ? bias[col] : 0.f;
            float b1 = bias ? bias[col + 1] : 0.f;
            if (r0 < M) {
                float2 v = make_float2(acc[ma][na][0] + b0, acc[ma][na][1] + b1);
                *(float2*)&Cuse[(size_t)r0 * N + col] = v;
            }
            if (r0 + 8 < M) {
                float2 v = make_float2(acc[ma][na][2] + b0, acc[ma][na][3] + b1);
                *(float2*)&Cuse[(size_t)(r0 + 8) * N + col] = v;
            }
        }
    }
}

// ---------------- attention logits: a_src/a_dst = <h[n,h,:], att> ----------------
template <int H>
__global__ void attdot_kernel(const float* __restrict__ h,
                              const float* __restrict__ att_src,
                              const float* __restrict__ att_dst,
                              float* __restrict__ a_src,
                              float* __restrict__ a_dst)
{
    int gw = (blockIdx.x * blockDim.x + threadIdx.x) >> 5;
    if (gw >= NN * H) return;
    int lane = threadIdx.x & 31;
    int node = gw / H, hh = gw % H;
    const float* row = h + (size_t)node * (H * DH) + hh * DH;
    float s1 = 0.f, s2 = 0.f;
#pragma unroll
    for (int c = lane; c < DH; c += 32) {
        float v = row[c];
        s1 += v * att_src[hh * DH + c];
        s2 += v * att_dst[hh * DH + c];
    }
#pragma unroll
    for (int o = 16; o > 0; o >>= 1) {
        s1 += __shfl_xor_sync(0xffffffffu, s1, o);
        s2 += __shfl_xor_sync(0xffffffffu, s2, o);
    }
    if (lane == 0) { a_src[gw] = s1; a_dst[gw] = s2; }
}

// ---------------- GAT aggregation: warp per dst node ----------------
template <int H, int ACT>
__global__ void gat_agg_kernel(const float* __restrict__ hfeat,
                               const float* __restrict__ a_src,
                               const float* __restrict__ a_dst,
                               const float* __restrict__ bias,
                               const float* __restrict__ gp,
                               const float* __restrict__ beta,
                               float* __restrict__ out)
{
    constexpr int F = H * DH;
    constexpr int R = F / 32;
    int warp = (blockIdx.x * blockDim.x + threadIdx.x) >> 5;
    if (warp >= NN) return;
    int lane = threadIdx.x & 31;
    int n = warp;
    int start = d_offs[n], end = d_offs[n + 1];

    float adst[H];
#pragma unroll
    for (int hh = 0; hh < H; hh++) adst[hh] = a_dst[n * H + hh];

    float m[H];
#pragma unroll
    for (int hh = 0; hh < H; hh++) m[hh] = -1e30f;
    for (int j = start + lane; j < end; j += 32) {
        int s = d_csr[j];
#pragma unroll
        for (int hh = 0; hh < H; hh++) {
            float e = a_src[s * H + hh] + adst[hh];
            e = e > 0.f ? e : 0.2f * e;
            m[hh] = fmaxf(m[hh], e);
        }
    }
#pragma unroll
    for (int hh = 0; hh < H; hh++)
#pragma unroll
        for (int o = 16; o > 0; o >>= 1)
            m[hh] = fmaxf(m[hh], __shfl_xor_sync(0xffffffffu, m[hh], o));

    float ssum[H] = {};
    for (int j = start + lane; j < end; j += 32) {
        int s = d_csr[j];
#pragma unroll
        for (int hh = 0; hh < H; hh++) {
            float e = a_src[s * H + hh] + adst[hh];
            e = e > 0.f ? e : 0.2f * e;
            ssum[hh] += __expf(e - m[hh]);
        }
    }
    float rinv[H];
#pragma unroll
    for (int hh = 0; hh < H; hh++) {
#pragma unroll
        for (int o = 16; o > 0; o >>= 1)
            ssum[hh] += __shfl_xor_sync(0xffffffffu, ssum[hh], o);
        rinv[hh] = 1.f / (ssum[hh] + 1e-16f);
    }

    float acc[R] = {};
    for (int jb = start; jb < end; jb += 32) {
        int j = jb + lane;
        int mys = 0;
        float myal[H];
#pragma unroll
        for (int hh = 0; hh < H; hh++) myal[hh] = 0.f;
        if (j < end) {
            mys = d_csr[j];
#pragma unroll
            for (int hh = 0; hh < H; hh++) {
                float e = a_src[mys * H + hh] + adst[hh];
                e = e > 0.f ? e : 0.2f * e;
                myal[hh] = __expf(e - m[hh]) * rinv[hh];
            }
        }
        int cnt = min(32, end - jb);
        for (int t = 0; t < cnt; t++) {
            int s = __shfl_sync(0xffffffffu, mys, t);
            float al[H];
#pragma unroll
            for (int hh = 0; hh < H; hh++)
                al[hh] = __shfl_sync(0xffffffffu, myal[hh], t);
            const float* hr = hfeat + (size_t)s * F;
#pragma unroll
            for (int r = 0; r < R; r++) {
                int f = r * 32 + lane;
                acc[r] += al[f / DH] * __ldg(&hr[f]);
            }
        }
    }

#pragma unroll
    for (int r = 0; r < R; r++) {
        int f = r * 32 + lane;
        float v = acc[r] + bias[f];
        if (ACT == 1) {
            v = v > 0.f ? v : (__expf(v) - 1.f);  // ELU
        } else {
            v = v + beta[0] * gp[(size_t)n * F + f];
        }
        out[(size_t)n * F + f] = v;
    }
}

// ---------------- launch ----------------
extern "C" void kernel_launch(void* const* d_in, const int* in_sizes, int n_in,
                              void* d_out, int out_size)
{
    const float* x       = (const float*)d_in[0];
    const int*   ei      = (const int*)d_in[1];
    const float* g       = (const float*)d_in[2];
    const float* proj_W  = (const float*)d_in[3];
    const float* proj_b  = (const float*)d_in[4];
    const float* gat1_W  = (const float*)d_in[5];
    const float* gat1_as = (const float*)d_in[6];
    const float* gat1_ad = (const float*)d_in[7];
    const float* gat1_b  = (const float*)d_in[8];
    const float* gat2_W  = (const float*)d_in[9];
    const float* gat2_as = (const float*)d_in[10];
    const float* gat2_ad = (const float*)d_in[11];
    const float* gat2_b  = (const float*)d_in[12];
    const float* dec_W   = (const float*)d_in[13];
    const float* dec_b   = (const float*)d_in[14];
    const float* beta    = (const float*)d_in[15];
    float* out = (float*)d_out;

    float *xp, *gp, *h1, *out1, *h2, *hin, *as1, *ad1, *as2, *ad2;
    cudaGetSymbolAddress((void**)&xp,   d_xp);
    cudaGetSymbolAddress((void**)&gp,   d_gp);
    cudaGetSymbolAddress((void**)&h1,   d_h1);
    cudaGetSymbolAddress((void**)&out1, d_out1);
    cudaGetSymbolAddress((void**)&h2,   d_h2);
    cudaGetSymbolAddress((void**)&hin,  d_hin);
    cudaGetSymbolAddress((void**)&as1,  d_as1);
    cudaGetSymbolAddress((void**)&ad1,  d_ad1);
    cudaGetSymbolAddress((void**)&as2,  d_as2);
    cudaGetSymbolAddress((void**)&ad2,  d_ad2);

    // graph build (CSR by dst, with self loops)
    zero_kernel<<<(NN + 255) / 256, 256>>>();
    hist_kernel<<<(TE + 255) / 256, 256>>>(ei);
    scan_kernel<<<1, 1024>>>();
    scatter_kernel<<<(TE + 255) / 256, 256>>>(ei);

    dim3 blk(256);
    int gm = (NN + BM - 1) / BM;  // 79

    // xp = x @ proj_W + b, gp = g @ proj_W + b  (fused via gridDim.z = 2)
    gemm_tf32<<<dim3(gm, DH / BN, 2), blk>>>(x, proj_W, proj_b, xp, NN, DH, DIN, g, gp);

    // gat1: h1 = xp @ gat1_W  [10000, 512]
    gemm_tf32<<<dim3(gm, (HEADS * DH) / BN, 1), blk>>>(xp, gat1_W, nullptr, h1, NN, HEADS * DH, DH);
    attdot_kernel<HEADS><<<(NN * HEADS * 32 + 255) / 256, 256>>>(h1, gat1_as, gat1_ad, as1, ad1);
    gat_agg_kernel<HEADS, 1><<<(NN * 32 + 255) / 256, 256>>>(h1, as1, ad1, gat1_b, nullptr, nullptr, out1);

    // gat2: h2 = out1 @ gat2_W  [10000, 128]
    gemm_tf32<<<dim3(gm, DH / BN, 1), blk>>>(out1, gat2_W, nullptr, h2, NN, DH, HEADS * DH);
    attdot_kernel<1><<<(NN * 32 + 255) / 256, 256>>>(h2, gat2_as, gat2_ad, as2, ad2);
    gat_agg_kernel<1, 2><<<(NN * 32 + 255) / 256, 256>>>(h2, as2, ad2, gat2_b, gp, beta, hin);

    // decoder: out = hin @ dec_W + dec_b  [10000, 768]
    gemm_tf32<<<dim3(gm, DIN / BN, 1), blk>>>(hin, dec_W, dec_b, out, NN, DIN, DH);
}

// round 4
// speedup vs baseline: 1.9939x; 1.0522x over previous
#include <cuda_runtime.h>

#define NN 10000
#define EE 160000
#define TE (EE + NN)
#define DIN 768
#define DH 128
#define HEADS 4

// ---------------- scratch (static device globals; no allocation) ----------------
__device__ float d_xp[NN * DH];
__device__ float d_gp[NN * DH];
__device__ float d_h1[NN * HEADS * DH];
__device__ float d_out1[NN * HEADS * DH];
__device__ float d_h2[NN * DH];
__device__ float d_hin[NN * DH];
__device__ float d_as1[NN * HEADS];
__device__ float d_ad1[NN * HEADS];
__device__ float d_as2[NN];
__device__ float d_ad2[NN];
__device__ float d_wbuf[TE * HEADS];
__device__ int d_deg[NN];
__device__ int d_offs[NN + 1];
__device__ int d_fill[NN];
__device__ int d_csr[TE];

// ---------------- graph build ----------------
__global__ void zero_kernel() {
    int i = blockIdx.x * blockDim.x + threadIdx.x;
    if (i < NN) {
        d_deg[i] = 0; d_fill[i] = 0;
        d_as2[i] = 0.f; d_ad2[i] = 0.f;
#pragma unroll
        for (int h = 0; h < HEADS; h++) {
            d_as1[i * HEADS + h] = 0.f;
            d_ad1[i * HEADS + h] = 0.f;
        }
    }
}

__global__ void hist_kernel(const int* __restrict__ ei) {
    int e = blockIdx.x * blockDim.x + threadIdx.x;
    if (e >= TE) return;
    int dst = (e < EE) ? ei[EE + e] : (e - EE);
    atomicAdd(&d_deg[dst], 1);
}

__global__ void scan_kernel() {
    __shared__ int wtot[32];
    int tid = threadIdx.x;
    int lane = tid & 31, wid = tid >> 5;
    const int CH = 10;  // 1024*10 >= 10000
    int base = tid * CH;
    int loc[CH];
    int s = 0;
#pragma unroll
    for (int i = 0; i < CH; i++) {
        int v = (base + i < NN) ? d_deg[base + i] : 0;
        loc[i] = s;
        s += v;
    }
    // inclusive warp scan of s
    int v = s;
#pragma unroll
    for (int off = 1; off < 32; off <<= 1) {
        int t = __shfl_up_sync(0xffffffffu, v, off);
        if (lane >= off) v += t;
    }
    if (lane == 31) wtot[wid] = v;
    __syncthreads();
    if (wid == 0) {
        int t = wtot[lane];
#pragma unroll
        for (int off = 1; off < 32; off <<= 1) {
            int u = __shfl_up_sync(0xffffffffu, t, off);
            if (lane >= off) t += u;
        }
        wtot[lane] = t;
    }
    __syncthreads();
    int pre = v - s + (wid > 0 ? wtot[wid - 1] : 0);  // exclusive over threads
#pragma unroll
    for (int i = 0; i < CH; i++)
        if (base + i < NN) d_offs[base + i] = pre + loc[i];
    if (tid == 1023) d_offs[NN] = wtot[31];
}

__global__ void scatter_kernel(const int* __restrict__ ei) {
    int e = blockIdx.x * blockDim.x + threadIdx.x;
    if (e >= TE) return;
    int src, dst;
    if (e < EE) { src = ei[e]; dst = ei[EE + e]; }
    else        { src = dst = e - EE; }
    int pos = d_offs[dst] + atomicAdd(&d_fill[dst], 1);
    d_csr[pos] = src;
}

// ---------------- TF32 tensor-core GEMM (+ optional fused att dots) ----------------
// C[M,N] = A[M,K] @ B[K,N] (+bias). BM=128, BN=64, BK=16.
// 256 threads = 8 warps (4 M x 2 N), warp tile 32x32 = 2x4 m16n8k8 atoms.
// If attS != nullptr: also accumulate aS[row*HH+head] += sum_col C*attS[col]
// (att flat-indexed by global column; one BN=64 block lies in a single head).
// If A2 != nullptr, blockIdx.z selects (A,C) vs (A2,C2) — shared weights.

#define BM 128
#define BN 64
#define BK 16
#define APAD 20
#define BPAD 72

__device__ __forceinline__ unsigned f2tf(float x) {
    unsigned r;
    asm("cvt.rna.tf32.f32 %0, %1;" : "=r"(r) : "f"(x));
    return r;
}

__device__ __forceinline__ void mma_tf32(float c[4], const unsigned a[4], const unsigned b[2]) {
    asm volatile(
        "mma.sync.aligned.m16n8k8.row.col.f32.tf32.tf32.f32 "
        "{%0,%1,%2,%3}, {%4,%5,%6,%7}, {%8,%9}, {%0,%1,%2,%3};\n"
        : "+f"(c[0]), "+f"(c[1]), "+f"(c[2]), "+f"(c[3])
        : "r"(a[0]), "r"(a[1]), "r"(a[2]), "r"(a[3]), "r"(b[0]), "r"(b[1]));
}

__global__ __launch_bounds__(256) void gemm_tf32(
    const float* __restrict__ A, const float* __restrict__ B,
    const float* __restrict__ bias, float* __restrict__ C,
    int M, int N, int K,
    const float* __restrict__ A2 = nullptr, float* __restrict__ C2 = nullptr,
    const float* __restrict__ attS = nullptr, const float* __restrict__ attD = nullptr,
    float* __restrict__ aS = nullptr, float* __restrict__ aD = nullptr, int HH = 1)
{
    __shared__ unsigned As[2][BM][APAD];
    __shared__ unsigned Bs[2][BK][BPAD];

    const float* Ause = A;
    float* Cuse = C;
    if (A2 != nullptr && blockIdx.z == 1) { Ause = A2; Cuse = C2; }

    int tid = threadIdx.x;
    int lane = tid & 31;
    int warp = tid >> 5;
    int wm = warp & 3;
    int wn = warp >> 2;
    int group = lane >> 2;   // 0..7
    int tig = lane & 3;      // 0..3

    int m0 = blockIdx.x * BM;
    int n0 = blockIdx.y * BN;

    int arow0 = tid >> 2;
    int acol = (tid & 3) * 4;
    int brow = tid >> 4;
    int bcol = (tid & 15) * 4;

    float4 av[2], bv;

    auto fetch = [&](int k0) {
#pragma unroll
        for (int it = 0; it < 2; it++) {
            int r = arow0 + it * 64;
            av[it] = make_float4(0.f, 0.f, 0.f, 0.f);
            if (m0 + r < M)
                av[it] = *(const float4*)&Ause[(size_t)(m0 + r) * K + k0 + acol];
        }
        bv = *(const float4*)&B[(size_t)(k0 + brow) * N + n0 + bcol];
    };
    auto stage = [&](int buf) {
#pragma unroll
        for (int it = 0; it < 2; it++) {
            int r = arow0 + it * 64;
            unsigned* p = &As[buf][r][acol];
            p[0] = f2tf(av[it].x); p[1] = f2tf(av[it].y);
            p[2] = f2tf(av[it].z); p[3] = f2tf(av[it].w);
        }
        unsigned* q = &Bs[buf][brow][bcol];
        q[0] = f2tf(bv.x); q[1] = f2tf(bv.y); q[2] = f2tf(bv.z); q[3] = f2tf(bv.w);
    };

    float acc[2][4][4] = {};

    fetch(0);
    stage(0);
    __syncthreads();

    int nk = K / BK;
    for (int i = 0; i < nk; i++) {
        int cur = i & 1;
        if (i + 1 < nk) fetch((i + 1) * BK);

#pragma unroll
        for (int ks = 0; ks < BK; ks += 8) {
            unsigned afr[2][4], bfr[4][2];
#pragma unroll
            for (int ma = 0; ma < 2; ma++) {
                int rb = wm * 32 + ma * 16;
                afr[ma][0] = As[cur][rb + group][ks + tig];
                afr[ma][1] = As[cur][rb + group + 8][ks + tig];
                afr[ma][2] = As[cur][rb + group][ks + tig + 4];
                afr[ma][3] = As[cur][rb + group + 8][ks + tig + 4];
            }
#pragma unroll
            for (int na = 0; na < 4; na++) {
                int cb = wn * 32 + na * 8 + group;
                bfr[na][0] = Bs[cur][ks + tig][cb];
                bfr[na][1] = Bs[cur][ks + tig + 4][cb];
            }
#pragma unroll
            for (int ma = 0; ma < 2; ma++)
#pragma unroll
                for (int na = 0; na < 4; na++)
                    mma_tf32(acc[ma][na], afr[ma], bfr[na]);
        }

        if (i + 1 < nk) stage(cur ^ 1);
        __syncthreads();
    }

    // epilogue: C write
#pragma unroll
    for (int ma = 0; ma < 2; ma++) {
        int r0 = m0 + wm * 32 + ma * 16 + group;
#pragma unroll
        for (int na = 0; na < 4; na++) {
            int col = n0 + wn * 32 + na * 8 + tig * 2;
            float b0 = bias ? bias[col] : 0.f;
            float b1 = bias ? bias[col + 1] : 0.f;
            if (r0 < M) {
                float2 v = make_float2(acc[ma][na][0] + b0, acc[ma][na][1] + b1);
                *(float2*)&Cuse[(size_t)r0 * N + col] = v;
            }
            if (r0 + 8 < M) {
                float2 v = make_float2(acc[ma][na][2] + b0, acc[ma][na][3] + b1);
                *(float2*)&Cuse[(size_t)(r0 + 8) * N + col] = v;
            }
        }
    }

    // fused attention dot products (gat GEMMs only; bias==nullptr there, acc is raw h)
    if (attS != nullptr) {
        int head = n0 / DH;
        float ps[2][2] = {}, pd[2][2] = {};
#pragma unroll
        for (int ma = 0; ma < 2; ma++)
#pragma unroll
            for (int na = 0; na < 4; na++) {
                int col = n0 + wn * 32 + na * 8 + tig * 2;
                float s0 = attS[col], s1 = attS[col + 1];
                float t0 = attD[col], t1 = attD[col + 1];
                ps[ma][0] += acc[ma][na][0] * s0 + acc[ma][na][1] * s1;
                ps[ma][1] += acc[ma][na][2] * s0 + acc[ma][na][3] * s1;
                pd[ma][0] += acc[ma][na][0] * t0 + acc[ma][na][1] * t1;
                pd[ma][1] += acc[ma][na][2] * t0 + acc[ma][na][3] * t1;
            }
#pragma unroll
        for (int ma = 0; ma < 2; ma++)
#pragma unroll
            for (int rr = 0; rr < 2; rr++) {
                float vs = ps[ma][rr], vd = pd[ma][rr];
                vs += __shfl_xor_sync(0xffffffffu, vs, 1);
                vs += __shfl_xor_sync(0xffffffffu, vs, 2);
                vd += __shfl_xor_sync(0xffffffffu, vd, 1);
                vd += __shfl_xor_sync(0xffffffffu, vd, 2);
                if (tig == 0) {
                    int row = m0 + wm * 32 + ma * 16 + group + rr * 8;
                    if (row < M) {
                        atomicAdd(&aS[row * HH + head], vs);
                        atomicAdd(&aD[row * HH + head], vd);
                    }
                }
            }
    }
}

// ---------------- GAT aggregation v2: warp per dst node, 2 passes ----------------
// Pass 1: per edge compute w = exp(leaky(a_src[s]+a_dst[n])) (no max-shift; logits
//         bounded ~|6|), store to d_wbuf in CSR order, accumulate row sum.
// Pass 2: gather features weighted by w, x4-unrolled neighbors; 1/sum folded into
//         the epilogue (hh = f/DH is uniform per register chunk).
template <int H, int ACT>
__global__ void gat_agg_kernel(const float* __restrict__ hfeat,
                               const float* __restrict__ a_src,
                               const float* __restrict__ a_dst,
                               const float* __restrict__ bias,
                               const float* __restrict__ gp,
                               const float* __restrict__ beta,
                               float* __restrict__ out)
{
    constexpr int F = H * DH;
    constexpr int R = F / 32;
    int warp = (blockIdx.x * blockDim.x + threadIdx.x) >> 5;
    if (warp >= NN) return;
    int lane = threadIdx.x & 31;
    int n = warp;
    int start = d_offs[n], end = d_offs[n + 1];

    float adst[H];
#pragma unroll
    for (int hh = 0; hh < H; hh++) adst[hh] = a_dst[n * H + hh];

    // pass 1: w = exp(leaky(e)), store; accumulate sum
    float ssum[H] = {};
    for (int j = start + lane; j < end; j += 32) {
        int s = d_csr[j];
        if (H == 4) {
            float4 a4 = *(const float4*)&a_src[s * 4];
            float e, w;
            float4 w4;
            e = a4.x + adst[0]; e = e > 0.f ? e : 0.2f * e; w = __expf(e); w4.x = w; ssum[0] += w;
            e = a4.y + adst[1]; e = e > 0.f ? e : 0.2f * e; w = __expf(e); w4.y = w; ssum[1] += w;
            e = a4.z + adst[2]; e = e > 0.f ? e : 0.2f * e; w = __expf(e); w4.z = w; ssum[2] += w;
            e = a4.w + adst[3]; e = e > 0.f ? e : 0.2f * e; w = __expf(e); w4.w = w; ssum[3] += w;
            *(float4*)&d_wbuf[(size_t)j * 4] = w4;
        } else {
            float e = a_src[s] + adst[0];
            e = e > 0.f ? e : 0.2f * e;
            float w = __expf(e);
            d_wbuf[j] = w;
            ssum[0] += w;
        }
    }
    float rinv[H];
#pragma unroll
    for (int hh = 0; hh < H; hh++) {
#pragma unroll
        for (int o = 16; o > 0; o >>= 1)
            ssum[hh] += __shfl_xor_sync(0xffffffffu, ssum[hh], o);
        rinv[hh] = 1.f / (ssum[hh] + 1e-16f);
    }
    __syncwarp();  // w buffer visibility across lanes

    // pass 2: weighted gather, x4 unrolled
    float acc[R] = {};
    int j = start;
    for (; j + 4 <= end; j += 4) {
        int s0 = d_csr[j], s1 = d_csr[j + 1], s2 = d_csr[j + 2], s3 = d_csr[j + 3];
        const float* h0 = hfeat + (size_t)s0 * F;
        const float* h1p = hfeat + (size_t)s1 * F;
        const float* h2p = hfeat + (size_t)s2 * F;
        const float* h3p = hfeat + (size_t)s3 * F;
        float wa0[H], wa1[H], wa2[H], wa3[H];
        if (H == 4) {
            float4 w0 = *(const float4*)&d_wbuf[(size_t)j * 4];
            float4 w1 = *(const float4*)&d_wbuf[(size_t)(j + 1) * 4];
            float4 w2 = *(const float4*)&d_wbuf[(size_t)(j + 2) * 4];
            float4 w3 = *(const float4*)&d_wbuf[(size_t)(j + 3) * 4];
            wa0[0] = w0.x; wa0[1] = w0.y; wa0[2] = w0.z; wa0[3] = w0.w;
            wa1[0] = w1.x; wa1[1] = w1.y; wa1[2] = w1.z; wa1[3] = w1.w;
            wa2[0] = w2.x; wa2[1] = w2.y; wa2[2] = w2.z; wa2[3] = w2.w;
            wa3[0] = w3.x; wa3[1] = w3.y; wa3[2] = w3.z; wa3[3] = w3.w;
        } else {
            wa0[0] = d_wbuf[j]; wa1[0] = d_wbuf[j + 1];
            wa2[0] = d_wbuf[j + 2]; wa3[0] = d_wbuf[j + 3];
        }
#pragma unroll
        for (int r = 0; r < R; r++) {
            int f = r * 32 + lane;
            int hh = (r * 32) / DH;
            acc[r] += wa0[hh] * __ldg(&h0[f]) + wa1[hh] * __ldg(&h1p[f])
                    + wa2[hh] * __ldg(&h2p[f]) + wa3[hh] * __ldg(&h3p[f]);
        }
    }
    for (; j < end; j++) {
        int s = d_csr[j];
        const float* hr = hfeat + (size_t)s * F;
        float wa[H];
        if (H == 4) {
            float4 w4 = *(const float4*)&d_wbuf[(size_t)j * 4];
            wa[0] = w4.x; wa[1] = w4.y; wa[2] = w4.z; wa[3] = w4.w;
        } else {
            wa[0] = d_wbuf[j];
        }
#pragma unroll
        for (int r = 0; r < R; r++) {
            int f = r * 32 + lane;
            int hh = (r * 32) / DH;
            acc[r] += wa[hh] * __ldg(&hr[f]);
        }
    }

    // epilogue
#pragma unroll
    for (int r = 0; r < R; r++) {
        int f = r * 32 + lane;
        int hh = (r * 32) / DH;
        float v = acc[r] * rinv[hh] + bias[f];
        if (ACT == 1) {
            v = v > 0.f ? v : (__expf(v) - 1.f);  // ELU
        } else {
            v = v + beta[0] * gp[(size_t)n * F + f];
        }
        out[(size_t)n * F + f] = v;
    }
}

// ---------------- launch ----------------
extern "C" void kernel_launch(void* const* d_in, const int* in_sizes, int n_in,
                              void* d_out, int out_size)
{
    const float* x       = (const float*)d_in[0];
    const int*   ei      = (const int*)d_in[1];
    const float* g       = (const float*)d_in[2];
    const float* proj_W  = (const float*)d_in[3];
    const float* proj_b  = (const float*)d_in[4];
    const float* gat1_W  = (const float*)d_in[5];
    const float* gat1_as = (const float*)d_in[6];
    const float* gat1_ad = (const float*)d_in[7];
    const float* gat1_b  = (const float*)d_in[8];
    const float* gat2_W  = (const float*)d_in[9];
    const float* gat2_as = (const float*)d_in[10];
    const float* gat2_ad = (const float*)d_in[11];
    const float* gat2_b  = (const float*)d_in[12];
    const float* dec_W   = (const float*)d_in[13];
    const float* dec_b   = (const float*)d_in[14];
    const float* beta    = (const float*)d_in[15];
    float* out = (float*)d_out;

    float *xp, *gp, *h1, *out1, *h2, *hin, *as1, *ad1, *as2, *ad2;
    cudaGetSymbolAddress((void**)&xp,   d_xp);
    cudaGetSymbolAddress((void**)&gp,   d_gp);
    cudaGetSymbolAddress((void**)&h1,   d_h1);
    cudaGetSymbolAddress((void**)&out1, d_out1);
    cudaGetSymbolAddress((void**)&h2,   d_h2);
    cudaGetSymbolAddress((void**)&hin,  d_hin);
    cudaGetSymbolAddress((void**)&as1,  d_as1);
    cudaGetSymbolAddress((void**)&ad1,  d_ad1);
    cudaGetSymbolAddress((void**)&as2,  d_as2);
    cudaGetSymbolAddress((void**)&ad2,  d_ad2);

    // graph build (CSR by dst, with self loops) + zero attn accumulators
    zero_kernel<<<(NN + 255) / 256, 256>>>();
    hist_kernel<<<(TE + 255) / 256, 256>>>(ei);
    scan_kernel<<<1, 1024>>>();
    scatter_kernel<<<(TE + 255) / 256, 256>>>(ei);

    dim3 blk(256);
    int gm = (NN + BM - 1) / BM;  // 79

    // xp = x @ proj_W + b, gp = g @ proj_W + b  (fused via gridDim.z = 2)
    gemm_tf32<<<dim3(gm, DH / BN, 2), blk>>>(x, proj_W, proj_b, xp, NN, DH, DIN, g, gp);

    // gat1: h1 = xp @ gat1_W  [10000, 512] + fused att dots
    gemm_tf32<<<dim3(gm, (HEADS * DH) / BN, 1), blk>>>(
        xp, gat1_W, nullptr, h1, NN, HEADS * DH, DH,
        nullptr, nullptr, gat1_as, gat1_ad, as1, ad1, HEADS);
    gat_agg_kernel<HEADS, 1><<<(NN * 32 + 255) / 256, 256>>>(h1, as1, ad1, gat1_b, nullptr, nullptr, out1);

    // gat2: h2 = out1 @ gat2_W  [10000, 128] + fused att dots
    gemm_tf32<<<dim3(gm, DH / BN, 1), blk>>>(
        out1, gat2_W, nullptr, h2, NN, DH, HEADS * DH,
        nullptr, nullptr, gat2_as, gat2_ad, as2, ad2, 1);
    gat_agg_kernel<1, 2><<<(NN * 32 + 255) / 256, 256>>>(h2, as2, ad2, gat2_b, gp, beta, hin);

    // decoder: out = hin @ dec_W + dec_b  [10000, 768]
    gemm_tf32<<<dim3(gm, DIN / BN, 1), blk>>>(hin, dec_W, dec_b, out, NN, DIN, DH);
}